// round 15
// baseline (speedup 1.0000x reference)
#include <cuda_runtime.h>
#include <cuda_fp16.h>
#include <cstdint>

// ---------------------------------------------------------------------------
// JKNet: 3x GraphConv(norm='both') + JK-cat + sum-pool + linear.
//
//   out = segment_sum((jk @ Wo)[src], dst) + bo          (linearity)
//   jk @ Wo = h1 @ Wo[0:128] + h2 @ Wo[128:256] + h3 @ Wo[256:384]
//
// R14 vs R13 (283us):
//   * Revert feats pre-conversion (net -8us): gemm1 converts fp32->fp16
//     in-flight (F32A template, plain loads); layers 2/3 keep the cp.async
//     double-buffered fp16 pipeline.
//   * Aggregation edge loop unrolled x8 (8 gathers in flight per half-warp).
// ---------------------------------------------------------------------------

#define N_MAX 100000
#define E_MAX 1600000
#define SCAN_B 1024
#define ASTRIDE 136     // halfs per smem tile row (17 x 16B -> conflict-free LDSM)
#define ABYTES (128 * ASTRIDE * 2)   // 34816 bytes per 128-row A tile
#define GEMM_GRID 296

__device__ int   g_out_deg[N_MAX];
__device__ int   g_in_deg [N_MAX];
__device__ float g_out_norm[N_MAX];
__device__ float g_in_norm [N_MAX];
__device__ int   g_row_start[N_MAX + 1];
__device__ int   g_cursor[N_MAX];
__device__ int   g_esrc[E_MAX];
__device__ int   g_bsums[1024];
__device__ int   g_boff [1024];

__device__ uint4 g_h1[N_MAX * 16];   // h layers fp16 (128 cols = 16 uint4)
__device__ uint4 g_h2[N_MAX * 16];
__device__ uint4 g_h3[N_MAX * 16];
__device__ uint4 g_yh[N_MAX * 16];   // messages fp16 (128 cols)
__device__ uint2 g_zh[N_MAX * 16];   // z messages fp16 (64 cols)
__device__ uint4 g_w0t[2048];        // W^T fp16 [n=128][k=128] (32KB)
__device__ uint4 g_w1t[2048];
__device__ uint4 g_w2t[2048];
__device__ uint4 g_wot[3072];        // Wo^T fp16 [n=64][k=384] (48KB)

// ---------------------------------------------------------------------------
// mma.sync / ldmatrix / cp.async helpers (all <= sm_80 PTX, valid on compute_100)
// ---------------------------------------------------------------------------

__device__ __forceinline__ void ldsm_x4(uint32_t& r0, uint32_t& r1,
                                        uint32_t& r2, uint32_t& r3, uint32_t addr) {
    asm volatile("ldmatrix.sync.aligned.m8n8.x4.shared.b16 {%0,%1,%2,%3}, [%4];"
                 : "=r"(r0), "=r"(r1), "=r"(r2), "=r"(r3) : "r"(addr));
}

__device__ __forceinline__ void mma16816(float* d, const uint32_t* a, const uint32_t* b) {
    asm volatile(
        "mma.sync.aligned.m16n8k16.row.col.f32.f16.f16.f32 "
        "{%0,%1,%2,%3}, {%4,%5,%6,%7}, {%8,%9}, {%0,%1,%2,%3};"
        : "+f"(d[0]), "+f"(d[1]), "+f"(d[2]), "+f"(d[3])
        : "r"(a[0]), "r"(a[1]), "r"(a[2]), "r"(a[3]), "r"(b[0]), "r"(b[1]));
}

__device__ __forceinline__ void cp16(uint32_t dst, const void* src, int srcsize) {
    asm volatile("cp.async.cg.shared.global [%0], [%1], 16, %2;"
                 :: "r"(dst), "l"(src), "r"(srcsize) : "memory");
}
#define CP_COMMIT() asm volatile("cp.async.commit_group;" ::: "memory")
#define CP_WAIT0()  asm volatile("cp.async.wait_group 0;" ::: "memory")
#define CP_WAIT1()  asm volatile("cp.async.wait_group 1;" ::: "memory")

// ---------------------------------------------------------------------------
// Degree / norm / CSR build
// ---------------------------------------------------------------------------

__global__ void k_zero_deg(int n) {
    int i = blockIdx.x * blockDim.x + threadIdx.x;
    if (i < n) { g_out_deg[i] = 0; g_in_deg[i] = 0; }
}

__global__ void k_count(const int4* __restrict__ src4, const int4* __restrict__ dst4,
                        int e) {
    int i = blockIdx.x * blockDim.x + threadIdx.x;
    int base = i * 4;
    if (base + 3 < e) {
        int4 s = src4[i], d = dst4[i];
        atomicAdd(&g_out_deg[s.x], 1); atomicAdd(&g_in_deg[d.x], 1);
        atomicAdd(&g_out_deg[s.y], 1); atomicAdd(&g_in_deg[d.y], 1);
        atomicAdd(&g_out_deg[s.z], 1); atomicAdd(&g_in_deg[d.z], 1);
        atomicAdd(&g_out_deg[s.w], 1); atomicAdd(&g_in_deg[d.w], 1);
    } else if (base < e) {
        const int* s = (const int*)src4;
        const int* d = (const int*)dst4;
        for (int j = base; j < e; ++j) {
            atomicAdd(&g_out_deg[s[j]], 1);
            atomicAdd(&g_in_deg [d[j]], 1);
        }
    }
}

// i < n: norms. i >= n: weight transpose+fp16 conversion (73728 elements).
__global__ void k_norm_cvt(const float* __restrict__ W0, const float* __restrict__ W1,
                           const float* __restrict__ W2, const float* __restrict__ Wo,
                           int n) {
    int i = blockIdx.x * blockDim.x + threadIdx.x;
    if (i < n) {
        float od = (float)g_out_deg[i];
        float id = (float)g_in_deg[i];
        g_out_norm[i] = od > 0.f ? rsqrtf(od) : 0.f;
        g_in_norm [i] = id > 0.f ? rsqrtf(id) : 0.f;
        return;
    }
    int j = i - n;
    if (j < 16384) {
        ((__half*)g_w0t)[j] = __float2half(W0[(j & 127) * 128 + (j >> 7)]);
    } else if (j < 32768) { j -= 16384;
        ((__half*)g_w1t)[j] = __float2half(W1[(j & 127) * 128 + (j >> 7)]);
    } else if (j < 49152) { j -= 32768;
        ((__half*)g_w2t)[j] = __float2half(W2[(j & 127) * 128 + (j >> 7)]);
    } else if (j < 73728) { j -= 49152;
        int nn = j / 384, kk = j % 384;
        ((__half*)g_wot)[j] = __float2half(Wo[kk * 64 + nn]);
    }
}

__device__ __forceinline__ int block_excl_scan(int v, int* warp_sums) {
    int t = threadIdx.x, lane = t & 31, w = t >> 5;
    int x = v;
#pragma unroll
    for (int o = 1; o < 32; o <<= 1) {
        int y = __shfl_up_sync(0xffffffff, x, o);
        if (lane >= o) x += y;
    }
    if (lane == 31) warp_sums[w] = x;
    __syncthreads();
    if (w == 0) {
        int s = warp_sums[lane];
#pragma unroll
        for (int o = 1; o < 32; o <<= 1) {
            int y = __shfl_up_sync(0xffffffff, s, o);
            if (lane >= o) s += y;
        }
        warp_sums[lane] = s;
    }
    __syncthreads();
    int woff = (w > 0) ? warp_sums[w - 1] : 0;
    return woff + x - v;
}

__global__ void __launch_bounds__(1024) k_bsums(int n) {
    __shared__ int ws[32];
    int i = blockIdx.x * SCAN_B + threadIdx.x;
    int v = (i < n) ? g_in_deg[i] : 0;
    int lane = threadIdx.x & 31, w = threadIdx.x >> 5;
#pragma unroll
    for (int o = 16; o > 0; o >>= 1) v += __shfl_down_sync(0xffffffff, v, o);
    if (lane == 0) ws[w] = v;
    __syncthreads();
    if (w == 0) {
        int s = ws[lane];
#pragma unroll
        for (int o = 16; o > 0; o >>= 1) s += __shfl_down_sync(0xffffffff, s, o);
        if (lane == 0) g_bsums[blockIdx.x] = s;
    }
}

__global__ void __launch_bounds__(1024) k_scan_bsums(int nb) {
    __shared__ int ws[32];
    int t = threadIdx.x;
    int v = (t < nb) ? g_bsums[t] : 0;
    int ex = block_excl_scan(v, ws);
    if (t < nb) g_boff[t] = ex;
}

__global__ void __launch_bounds__(1024) k_write_csr(int n) {
    __shared__ int ws[32];
    int i = blockIdx.x * SCAN_B + threadIdx.x;
    int v = (i < n) ? g_in_deg[i] : 0;
    int ex = block_excl_scan(v, ws) + g_boff[blockIdx.x];
    if (i < n) {
        g_row_start[i] = ex;
        g_cursor[i]    = ex;
        if (i == n - 1) g_row_start[n] = ex + v;
    }
}

__global__ void k_fill(const int4* __restrict__ src4, const int4* __restrict__ dst4,
                       int e) {
    int i = blockIdx.x * blockDim.x + threadIdx.x;
    int base = i * 4;
    if (base + 3 < e) {
        int4 s = src4[i], d = dst4[i];
        g_esrc[atomicAdd(&g_cursor[d.x], 1)] = s.x;
        g_esrc[atomicAdd(&g_cursor[d.y], 1)] = s.y;
        g_esrc[atomicAdd(&g_cursor[d.z], 1)] = s.z;
        g_esrc[atomicAdd(&g_cursor[d.w], 1)] = s.w;
    } else if (base < e) {
        const int* s = (const int*)src4;
        const int* d = (const int*)dst4;
        for (int j = base; j < e; ++j)
            g_esrc[atomicAdd(&g_cursor[d[j]], 1)] = s[j];
    }
}

// ---------------------------------------------------------------------------
// A-tile loaders
// ---------------------------------------------------------------------------

__device__ __forceinline__ void issue_tileA(const uint4* __restrict__ A,
                                            uint32_t sbase, int row0, int n) {
    int tid = threadIdx.x;
#pragma unroll
    for (int i = tid; i < 2048; i += 256) {
        int r = i >> 4, g = i & 15;
        int row = row0 + r;
        const uint4* src = A + (size_t)((row < n) ? row : 0) * 16 + g;
        int sz = (row < n) ? 16 : 0;
        cp16(sbase + (r * ASTRIDE + g * 8) * 2, src, sz);
    }
}

// fp32 source: plain loads + in-flight conversion (layer 1 feats).
__device__ __forceinline__ void load_tileA_f32(const float* __restrict__ A,
                                               __half* __restrict__ sA,
                                               int row0, int n) {
    int tid = threadIdx.x;
#pragma unroll
    for (int i = tid; i < 2048; i += 256) {
        int r = i >> 4, g = i & 15;
        uint4 av = make_uint4(0, 0, 0, 0);
        if (row0 + r < n) {
            const float4* f4 = (const float4*)A + (size_t)(row0 + r) * 32 + g * 2;
            float4 x0 = f4[0], x1 = f4[1];
            __half2 h0 = __floats2half2_rn(x0.x, x0.y);
            __half2 h1 = __floats2half2_rn(x0.z, x0.w);
            __half2 h2 = __floats2half2_rn(x1.x, x1.y);
            __half2 h3 = __floats2half2_rn(x1.z, x1.w);
            av = make_uint4(*(unsigned*)&h0, *(unsigned*)&h1,
                            *(unsigned*)&h2, *(unsigned*)&h3);
        }
        *(uint4*)(sA + r * ASTRIDE + g * 8) = av;
    }
}

// ---------------------------------------------------------------------------
// tc_gemm (persistent): y[r,:] = fp16( out_norm[r] * (A[r,:] @ Wt^T) ).
// F32A=true: in-flight convert (no cp.async). F32A=false: cp.async dbl-buffer.
// Warp grid 4m x 2n, warp tile 32x64, mma.sync.m16n8k16, fp32 accum.
// ---------------------------------------------------------------------------

#define SMEM_GEMM  (3 * ABYTES)                      // 104448
#define SMEM_GEMMZ (2 * ABYTES + 192 * ASTRIDE * 2)  // 121856

template <bool F32A>
__global__ void __launch_bounds__(256, 2)
tc_gemm(const void* __restrict__ Ain, const uint4* __restrict__ Bt,
        unsigned* __restrict__ yh, int n) {
    extern __shared__ char ds[];
    __half* sB = (__half*)(ds + 2 * ABYTES);

    int tid = threadIdx.x, lane = tid & 31, wid = tid >> 5;

    // B tile once per CTA.
#pragma unroll
    for (int i = tid; i < 2048; i += 256) {
        int r = i >> 4, g = i & 15;
        *(uint4*)(sB + r * ASTRIDE + g * 8) = Bt[i];
    }

    uint32_t sA0 = (uint32_t)__cvta_generic_to_shared(ds);
    uint32_t sBb = (uint32_t)__cvta_generic_to_shared(sB);
    int wm = (wid & 3) * 32;
    int wn = (wid >> 2) * 64;
    int g = lane >> 2, t = lane & 3;

    int nblk = (n + 127) >> 7;
    int rb0 = blockIdx.x;

    if (!F32A) {
        if (rb0 < nblk) issue_tileA((const uint4*)Ain, sA0, rb0 * 128, n);
        CP_COMMIT();
    }

    int cur = 0;
    for (int rb = rb0; rb < nblk; rb += gridDim.x) {
        int row0 = rb * 128;

        if (F32A) {
            __syncthreads();
            load_tileA_f32((const float*)Ain, (__half*)ds, row0, n);
            __syncthreads();
        } else {
            int nxt = rb + gridDim.x;
            if (nxt < nblk) {
                issue_tileA((const uint4*)Ain, sA0 + (cur ^ 1) * ABYTES, nxt * 128, n);
                CP_COMMIT();
                CP_WAIT1();
            } else {
                CP_WAIT0();
            }
            __syncthreads();
        }
        uint32_t sAb = F32A ? sA0 : (sA0 + cur * ABYTES);

        float acc[2][8][4];
#pragma unroll
        for (int mt = 0; mt < 2; ++mt)
#pragma unroll
            for (int nt = 0; nt < 8; ++nt)
#pragma unroll
                for (int q = 0; q < 4; ++q) acc[mt][nt][q] = 0.f;

#pragma unroll
        for (int k0 = 0; k0 < 128; k0 += 16) {
            uint32_t a[2][4];
#pragma unroll
            for (int mt = 0; mt < 2; ++mt) {
                int row = wm + mt * 16 + (lane & 15);
                int col = k0 + (lane >> 4) * 8;
                ldsm_x4(a[mt][0], a[mt][1], a[mt][2], a[mt][3],
                        sAb + (row * ASTRIDE + col) * 2);
            }
#pragma unroll
            for (int np = 0; np < 4; ++np) {
                int nb = wn + np * 16;
                int q  = lane >> 3;
                int nrow = nb + ((q >> 1) << 3) + (lane & 7);
                int ncol = k0 + ((q & 1) << 3);
                uint32_t b[4];
                ldsm_x4(b[0], b[1], b[2], b[3], sBb + (nrow * ASTRIDE + ncol) * 2);
                mma16816(acc[0][2 * np],     a[0], b);
                mma16816(acc[1][2 * np],     a[1], b);
                mma16816(acc[0][2 * np + 1], a[0], b + 2);
                mma16816(acc[1][2 * np + 1], a[1], b + 2);
            }
        }

#pragma unroll
        for (int mt = 0; mt < 2; ++mt) {
            int rl = row0 + wm + mt * 16 + g;
            int rh = rl + 8;
            float sl = (rl < n) ? g_out_norm[rl] : 0.f;
            float sh = (rh < n) ? g_out_norm[rh] : 0.f;
#pragma unroll
            for (int nt = 0; nt < 8; ++nt) {
                int c = wn + nt * 8 + t * 2;
                if (rl < n) {
                    __half2 p = __floats2half2_rn(acc[mt][nt][0] * sl, acc[mt][nt][1] * sl);
                    yh[rl * 64 + (c >> 1)] = *(unsigned*)&p;
                }
                if (rh < n) {
                    __half2 p = __floats2half2_rn(acc[mt][nt][2] * sh, acc[mt][nt][3] * sh);
                    yh[rh * 64 + (c >> 1)] = *(unsigned*)&p;
                }
            }
        }
        if (!F32A) { __syncthreads(); cur ^= 1; }
    }
}

// ---------------------------------------------------------------------------
// tc_gemm_z (persistent, double-buffered over (rb,p)): z = fp16(sum_p hp@Wop).
// ---------------------------------------------------------------------------

__global__ void __launch_bounds__(256)
tc_gemm_z(const uint4* __restrict__ H1, const uint4* __restrict__ H2,
          const uint4* __restrict__ H3, unsigned* __restrict__ zh, int n) {
    extern __shared__ char ds[];
    __half* sB = (__half*)(ds + 2 * ABYTES);

    int tid = threadIdx.x, lane = tid & 31, wid = tid >> 5;

#pragma unroll
    for (int i = tid; i < 3072; i += 256) {
        int p = i >> 10, rem = i & 1023;
        int r = rem >> 4, g = rem & 15;
        *(uint4*)(sB + (p * 64 + r) * ASTRIDE + g * 8) = g_wot[r * 48 + p * 16 + g];
    }

    uint32_t sA0 = (uint32_t)__cvta_generic_to_shared(ds);
    uint32_t sBb = (uint32_t)__cvta_generic_to_shared(sB);
    int wm = (wid & 3) * 32;
    int wn = (wid >> 2) * 32;
    int g = lane >> 2, t = lane & 3;

    const uint4* parts[3] = { H1, H2, H3 };
    int nblk = (n + 127) >> 7;
    int rb0 = blockIdx.x;

    if (rb0 < nblk) issue_tileA(parts[0], sA0, rb0 * 128, n);
    CP_COMMIT();

    int cur = 0;
    float acc[2][4][4];

    for (int rb = rb0; rb < nblk; rb += gridDim.x) {
        int row0 = rb * 128;
        for (int p = 0; p < 3; ++p) {
            int np_ = p + 1, nrb = rb;
            if (np_ == 3) { np_ = 0; nrb = rb + gridDim.x; }
            if (nrb < nblk) {
                issue_tileA(parts[np_], sA0 + (cur ^ 1) * ABYTES, nrb * 128, n);
                CP_COMMIT();
                CP_WAIT1();
            } else {
                CP_WAIT0();
            }
            __syncthreads();
            uint32_t sAb = sA0 + cur * ABYTES;

            if (p == 0) {
#pragma unroll
                for (int mt = 0; mt < 2; ++mt)
#pragma unroll
                    for (int nt = 0; nt < 4; ++nt)
#pragma unroll
                        for (int q = 0; q < 4; ++q) acc[mt][nt][q] = 0.f;
            }

#pragma unroll
            for (int k0 = 0; k0 < 128; k0 += 16) {
                uint32_t a[2][4];
#pragma unroll
                for (int mt = 0; mt < 2; ++mt) {
                    int row = wm + mt * 16 + (lane & 15);
                    int col = k0 + (lane >> 4) * 8;
                    ldsm_x4(a[mt][0], a[mt][1], a[mt][2], a[mt][3],
                            sAb + (row * ASTRIDE + col) * 2);
                }
#pragma unroll
                for (int np2 = 0; np2 < 2; ++np2) {
                    int nb = p * 64 + wn + np2 * 16;
                    int q  = lane >> 3;
                    int nrow = nb + ((q >> 1) << 3) + (lane & 7);
                    int ncol = k0 + ((q & 1) << 3);
                    uint32_t b[4];
                    ldsm_x4(b[0], b[1], b[2], b[3], sBb + (nrow * ASTRIDE + ncol) * 2);
                    mma16816(acc[0][2 * np2],     a[0], b);
                    mma16816(acc[1][2 * np2],     a[1], b);
                    mma16816(acc[0][2 * np2 + 1], a[0], b + 2);
                    mma16816(acc[1][2 * np2 + 1], a[1], b + 2);
                }
            }

            if (p == 2) {
#pragma unroll
                for (int mt = 0; mt < 2; ++mt) {
                    int rl = row0 + wm + mt * 16 + g;
                    int rh = rl + 8;
#pragma unroll
                    for (int nt = 0; nt < 4; ++nt) {
                        int c = wn + nt * 8 + t * 2;
                        if (rl < n) {
                            __half2 pp = __floats2half2_rn(acc[mt][nt][0], acc[mt][nt][1]);
                            zh[rl * 32 + (c >> 1)] = *(unsigned*)&pp;
                        }
                        if (rh < n) {
                            __half2 pp = __floats2half2_rn(acc[mt][nt][2], acc[mt][nt][3]);
                            zh[rh * 32 + (c >> 1)] = *(unsigned*)&pp;
                        }
                    }
                }
            }
            __syncthreads();
            cur ^= 1;
        }
    }
}

// ---------------------------------------------------------------------------
// Aggregation (128-wide): half-warp per node, 8-deep gather pipeline.
// ---------------------------------------------------------------------------

__device__ __forceinline__ void add_h8(float* acc, uint4 u) {
    float2 f0 = __half22float2(*(__half2*)&u.x);
    float2 f1 = __half22float2(*(__half2*)&u.y);
    float2 f2 = __half22float2(*(__half2*)&u.z);
    float2 f3 = __half22float2(*(__half2*)&u.w);
    acc[0] += f0.x; acc[1] += f0.y; acc[2] += f1.x; acc[3] += f1.y;
    acc[4] += f2.x; acc[5] += f2.y; acc[6] += f3.x; acc[7] += f3.y;
}

__global__ void __launch_bounds__(256) agg128(const uint4* __restrict__ yh4,
                                              const float* __restrict__ bias,
                                              uint4* __restrict__ h, int n) {
    int node = (blockIdx.x * blockDim.x + threadIdx.x) >> 4;
    int l    = threadIdx.x & 15;
    if (node >= n) return;

    int s0 = g_row_start[node];
    int s1 = g_row_start[node + 1];

    float acc[8] = {0.f, 0.f, 0.f, 0.f, 0.f, 0.f, 0.f, 0.f};
    int e = s0;
    for (; e + 8 <= s1; e += 8) {
        int idx[8];
#pragma unroll
        for (int q = 0; q < 8; ++q) idx[q] = __ldg(&g_esrc[e + q]);
        uint4 v[8];
#pragma unroll
        for (int q = 0; q < 8; ++q) v[q] = yh4[idx[q] * 16 + l];
#pragma unroll
        for (int q = 0; q < 8; ++q) add_h8(acc, v[q]);
    }
    for (; e + 2 <= s1; e += 2) {
        int i0 = __ldg(&g_esrc[e]);
        int i1 = __ldg(&g_esrc[e + 1]);
        uint4 a = yh4[i0 * 16 + l];
        uint4 b = yh4[i1 * 16 + l];
        add_h8(acc, a); add_h8(acc, b);
    }
    for (; e < s1; ++e) add_h8(acc, yh4[__ldg(&g_esrc[e]) * 16 + l]);

    float nv = g_in_norm[node];
    float4 b0 = ((const float4*)bias)[2 * l];
    float4 b1 = ((const float4*)bias)[2 * l + 1];
    float o0 = fmaxf(acc[0] * nv + b0.x, 0.f);
    float o1 = fmaxf(acc[1] * nv + b0.y, 0.f);
    float o2 = fmaxf(acc[2] * nv + b0.z, 0.f);
    float o3 = fmaxf(acc[3] * nv + b0.w, 0.f);
    float o4 = fmaxf(acc[4] * nv + b1.x, 0.f);
    float o5 = fmaxf(acc[5] * nv + b1.y, 0.f);
    float o6 = fmaxf(acc[6] * nv + b1.z, 0.f);
    float o7 = fmaxf(acc[7] * nv + b1.w, 0.f);
    __half2 p0 = __floats2half2_rn(o0, o1);
    __half2 p1 = __floats2half2_rn(o2, o3);
    __half2 p2 = __floats2half2_rn(o4, o5);
    __half2 p3 = __floats2half2_rn(o6, o7);
    h[node * 16 + l] = make_uint4(*(unsigned*)&p0, *(unsigned*)&p1,
                                  *(unsigned*)&p2, *(unsigned*)&p3);
}

// ---------------------------------------------------------------------------
// Final pooling (64-wide): half-warp per node, 8-deep pipeline, fp32 out.
// ---------------------------------------------------------------------------

__device__ __forceinline__ void add_h4z(float4& acc, uint2 u) {
    float2 f0 = __half22float2(*(__half2*)&u.x);
    float2 f1 = __half22float2(*(__half2*)&u.y);
    acc.x += f0.x; acc.y += f0.y; acc.z += f1.x; acc.w += f1.y;
}

__global__ void __launch_bounds__(256) agg64(const uint2* __restrict__ zh2,
                                             const float* __restrict__ bo,
                                             float* __restrict__ out, int n) {
    int node = (blockIdx.x * blockDim.x + threadIdx.x) >> 4;
    int l    = threadIdx.x & 15;
    if (node >= n) return;

    int s0 = g_row_start[node];
    int s1 = g_row_start[node + 1];

    float4 acc = make_float4(0.f, 0.f, 0.f, 0.f);
    int e = s0;
    for (; e + 8 <= s1; e += 8) {
        int idx[8];
#pragma unroll
        for (int q = 0; q < 8; ++q) idx[q] = __ldg(&g_esrc[e + q]);
        uint2 v[8];
#pragma unroll
        for (int q = 0; q < 8; ++q) v[q] = zh2[idx[q] * 16 + l];
#pragma unroll
        for (int q = 0; q < 8; ++q) add_h4z(acc, v[q]);
    }
    for (; e < s1; ++e) add_h4z(acc, zh2[__ldg(&g_esrc[e]) * 16 + l]);

    float4 bb = ((const float4*)bo)[l];
    ((float4*)out)[node * 16 + l] =
        make_float4(acc.x + bb.x, acc.y + bb.y, acc.z + bb.z, acc.w + bb.w);
}

// ---------------------------------------------------------------------------
// Launcher
// ---------------------------------------------------------------------------

extern "C" void kernel_launch(void* const* d_in, const int* in_sizes, int n_in,
                              void* d_out, int out_size) {
    const float* feats = (const float*)d_in[0];
    const int*   src   = (const int*)  d_in[1];
    const int*   dst   = (const int*)  d_in[2];
    const float* W0    = (const float*)d_in[3];
    const float* b0    = (const float*)d_in[4];
    const float* W1    = (const float*)d_in[5];
    const float* b1    = (const float*)d_in[6];
    const float* W2    = (const float*)d_in[7];
    const float* b2    = (const float*)d_in[8];
    const float* Wo    = (const float*)d_in[9];
    const float* bo    = (const float*)d_in[10];
    float* out = (float*)d_out;

    int n = in_sizes[0] / 128;
    int e = in_sizes[1];

    cudaFuncSetAttribute(tc_gemm<true>,  cudaFuncAttributeMaxDynamicSharedMemorySize, SMEM_GEMM);
    cudaFuncSetAttribute(tc_gemm<false>, cudaFuncAttributeMaxDynamicSharedMemorySize, SMEM_GEMM);
    cudaFuncSetAttribute(tc_gemm_z,      cudaFuncAttributeMaxDynamicSharedMemorySize, SMEM_GEMMZ);

    uint4 *h1, *h2, *h3, *yh4, *w0t, *w1t, *w2t;
    uint2 *zh2;
    cudaGetSymbolAddress((void**)&h1,  g_h1);
    cudaGetSymbolAddress((void**)&h2,  g_h2);
    cudaGetSymbolAddress((void**)&h3,  g_h3);
    cudaGetSymbolAddress((void**)&yh4, g_yh);
    cudaGetSymbolAddress((void**)&zh2, g_zh);
    cudaGetSymbolAddress((void**)&w0t, g_w0t);
    cudaGetSymbolAddress((void**)&w1t, g_w1t);
    cudaGetSymbolAddress((void**)&w2t, g_w2t);

    int nb  = (n + 255) / 256;
    int eb4 = (e / 4 + 255) / 256;
    int sb  = (n + SCAN_B - 1) / SCAN_B;
    int cb  = (n + 73728 + 255) / 256;    // norms + weight conversion
    int ab  = (n + 15) / 16;

    // Degrees -> norms+weights -> gemm1 (4th launch, profiled) -> CSR.
    k_zero_deg<<<nb, 256>>>(n);
    k_count<<<eb4, 256>>>((const int4*)src, (const int4*)dst, e);
    k_norm_cvt<<<cb, 256>>>(W0, W1, W2, Wo, n);
    tc_gemm<true><<<GEMM_GRID, 256, SMEM_GEMM>>>(feats, w0t, (unsigned*)yh4, n);
    k_bsums<<<sb, 1024>>>(n);
    k_scan_bsums<<<1, 1024>>>(sb);
    k_write_csr<<<sb, 1024>>>(n);
    k_fill<<<eb4, 256>>>((const int4*)src, (const int4*)dst, e);

    // Layer 1 aggregation -> h1 (fp16)
    agg128<<<ab, 256>>>(yh4, b0, h1, n);
    // Layer 2
    tc_gemm<false><<<GEMM_GRID, 256, SMEM_GEMM>>>(h1, w1t, (unsigned*)yh4, n);
    agg128<<<ab, 256>>>(yh4, b1, h2, n);
    // Layer 3
    tc_gemm<false><<<GEMM_GRID, 256, SMEM_GEMM>>>(h2, w2t, (unsigned*)yh4, n);
    agg128<<<ab, 256>>>(yh4, b2, h3, n);

    // Output projection (JK-cat folded) + final pooling
    tc_gemm_z<<<148, 256, SMEM_GEMMZ>>>(h1, h2, h3, (unsigned*)zh2, n);
    agg64<<<ab, 256>>>(zh2, bo, out, n);
}

// round 16
// speedup vs baseline: 1.0394x; 1.0394x over previous
#include <cuda_runtime.h>
#include <cuda_fp16.h>
#include <cstdint>

// ---------------------------------------------------------------------------
// JKNet: 3x GraphConv(norm='both') + JK-cat + sum-pool + linear.
//
//   out = segment_sum((jk @ Wo)[src], dst) + bo          (linearity)
//   jk @ Wo = h1 @ Wo[0:128] + h2 @ Wo[128:256] + h3 @ Wo[256:384]
//
// R15 = recombination of measured-best configs:
//   * gemm1: R12 exact kernel (single A buffer, 69.6KB smem, in-flight
//     fp32->fp16 convert) - measured 28.2us.
//   * gemm2/3: R13 cp.async double-buffered fp16 kernel - measured 22.8us.
//   * gemm_z: R13 cp.async version (grid 148).
//   * aggs: R12 x4-unroll half-warp versions.
// ---------------------------------------------------------------------------

#define N_MAX 100000
#define E_MAX 1600000
#define SCAN_B 1024
#define ASTRIDE 136     // halfs per smem tile row (17 x 16B -> conflict-free LDSM)
#define ABYTES (128 * ASTRIDE * 2)   // 34816 bytes per 128-row A tile
#define GEMM_GRID 296

__device__ int   g_out_deg[N_MAX];
__device__ int   g_in_deg [N_MAX];
__device__ float g_out_norm[N_MAX];
__device__ float g_in_norm [N_MAX];
__device__ int   g_row_start[N_MAX + 1];
__device__ int   g_cursor[N_MAX];
__device__ int   g_esrc[E_MAX];
__device__ int   g_bsums[1024];
__device__ int   g_boff [1024];

__device__ uint4 g_h1[N_MAX * 16];   // h layers fp16 (128 cols = 16 uint4)
__device__ uint4 g_h2[N_MAX * 16];
__device__ uint4 g_h3[N_MAX * 16];
__device__ uint4 g_yh[N_MAX * 16];   // messages fp16 (128 cols)
__device__ uint2 g_zh[N_MAX * 16];   // z messages fp16 (64 cols)
__device__ uint4 g_w0t[2048];        // W^T fp16 [n=128][k=128] (32KB)
__device__ uint4 g_w1t[2048];
__device__ uint4 g_w2t[2048];
__device__ uint4 g_wot[3072];        // Wo^T fp16 [n=64][k=384] (48KB)

// ---------------------------------------------------------------------------
// mma.sync / ldmatrix / cp.async helpers (all <= sm_80 PTX, valid on compute_100)
// ---------------------------------------------------------------------------

__device__ __forceinline__ void ldsm_x4(uint32_t& r0, uint32_t& r1,
                                        uint32_t& r2, uint32_t& r3, uint32_t addr) {
    asm volatile("ldmatrix.sync.aligned.m8n8.x4.shared.b16 {%0,%1,%2,%3}, [%4];"
                 : "=r"(r0), "=r"(r1), "=r"(r2), "=r"(r3) : "r"(addr));
}

__device__ __forceinline__ void mma16816(float* d, const uint32_t* a, const uint32_t* b) {
    asm volatile(
        "mma.sync.aligned.m16n8k16.row.col.f32.f16.f16.f32 "
        "{%0,%1,%2,%3}, {%4,%5,%6,%7}, {%8,%9}, {%0,%1,%2,%3};"
        : "+f"(d[0]), "+f"(d[1]), "+f"(d[2]), "+f"(d[3])
        : "r"(a[0]), "r"(a[1]), "r"(a[2]), "r"(a[3]), "r"(b[0]), "r"(b[1]));
}

__device__ __forceinline__ void cp16(uint32_t dst, const void* src, int srcsize) {
    asm volatile("cp.async.cg.shared.global [%0], [%1], 16, %2;"
                 :: "r"(dst), "l"(src), "r"(srcsize) : "memory");
}
#define CP_COMMIT() asm volatile("cp.async.commit_group;" ::: "memory")
#define CP_WAIT0()  asm volatile("cp.async.wait_group 0;" ::: "memory")
#define CP_WAIT1()  asm volatile("cp.async.wait_group 1;" ::: "memory")

// ---------------------------------------------------------------------------
// Degree / norm / CSR build
// ---------------------------------------------------------------------------

__global__ void k_zero_deg(int n) {
    int i = blockIdx.x * blockDim.x + threadIdx.x;
    if (i < n) { g_out_deg[i] = 0; g_in_deg[i] = 0; }
}

__global__ void k_count(const int4* __restrict__ src4, const int4* __restrict__ dst4,
                        int e) {
    int i = blockIdx.x * blockDim.x + threadIdx.x;
    int base = i * 4;
    if (base + 3 < e) {
        int4 s = src4[i], d = dst4[i];
        atomicAdd(&g_out_deg[s.x], 1); atomicAdd(&g_in_deg[d.x], 1);
        atomicAdd(&g_out_deg[s.y], 1); atomicAdd(&g_in_deg[d.y], 1);
        atomicAdd(&g_out_deg[s.z], 1); atomicAdd(&g_in_deg[d.z], 1);
        atomicAdd(&g_out_deg[s.w], 1); atomicAdd(&g_in_deg[d.w], 1);
    } else if (base < e) {
        const int* s = (const int*)src4;
        const int* d = (const int*)dst4;
        for (int j = base; j < e; ++j) {
            atomicAdd(&g_out_deg[s[j]], 1);
            atomicAdd(&g_in_deg [d[j]], 1);
        }
    }
}

// i < n: norms. i >= n: weight transpose+fp16 conversion (73728 elements).
__global__ void k_norm_cvt(const float* __restrict__ W0, const float* __restrict__ W1,
                           const float* __restrict__ W2, const float* __restrict__ Wo,
                           int n) {
    int i = blockIdx.x * blockDim.x + threadIdx.x;
    if (i < n) {
        float od = (float)g_out_deg[i];
        float id = (float)g_in_deg[i];
        g_out_norm[i] = od > 0.f ? rsqrtf(od) : 0.f;
        g_in_norm [i] = id > 0.f ? rsqrtf(id) : 0.f;
        return;
    }
    int j = i - n;
    if (j < 16384) {
        ((__half*)g_w0t)[j] = __float2half(W0[(j & 127) * 128 + (j >> 7)]);
    } else if (j < 32768) { j -= 16384;
        ((__half*)g_w1t)[j] = __float2half(W1[(j & 127) * 128 + (j >> 7)]);
    } else if (j < 49152) { j -= 32768;
        ((__half*)g_w2t)[j] = __float2half(W2[(j & 127) * 128 + (j >> 7)]);
    } else if (j < 73728) { j -= 49152;
        int nn = j / 384, kk = j % 384;
        ((__half*)g_wot)[j] = __float2half(Wo[kk * 64 + nn]);
    }
}

__device__ __forceinline__ int block_excl_scan(int v, int* warp_sums) {
    int t = threadIdx.x, lane = t & 31, w = t >> 5;
    int x = v;
#pragma unroll
    for (int o = 1; o < 32; o <<= 1) {
        int y = __shfl_up_sync(0xffffffff, x, o);
        if (lane >= o) x += y;
    }
    if (lane == 31) warp_sums[w] = x;
    __syncthreads();
    if (w == 0) {
        int s = warp_sums[lane];
#pragma unroll
        for (int o = 1; o < 32; o <<= 1) {
            int y = __shfl_up_sync(0xffffffff, s, o);
            if (lane >= o) s += y;
        }
        warp_sums[lane] = s;
    }
    __syncthreads();
    int woff = (w > 0) ? warp_sums[w - 1] : 0;
    return woff + x - v;
}

__global__ void __launch_bounds__(1024) k_bsums(int n) {
    __shared__ int ws[32];
    int i = blockIdx.x * SCAN_B + threadIdx.x;
    int v = (i < n) ? g_in_deg[i] : 0;
    int lane = threadIdx.x & 31, w = threadIdx.x >> 5;
#pragma unroll
    for (int o = 16; o > 0; o >>= 1) v += __shfl_down_sync(0xffffffff, v, o);
    if (lane == 0) ws[w] = v;
    __syncthreads();
    if (w == 0) {
        int s = ws[lane];
#pragma unroll
        for (int o = 16; o > 0; o >>= 1) s += __shfl_down_sync(0xffffffff, s, o);
        if (lane == 0) g_bsums[blockIdx.x] = s;
    }
}

__global__ void __launch_bounds__(1024) k_scan_bsums(int nb) {
    __shared__ int ws[32];
    int t = threadIdx.x;
    int v = (t < nb) ? g_bsums[t] : 0;
    int ex = block_excl_scan(v, ws);
    if (t < nb) g_boff[t] = ex;
}

__global__ void __launch_bounds__(1024) k_write_csr(int n) {
    __shared__ int ws[32];
    int i = blockIdx.x * SCAN_B + threadIdx.x;
    int v = (i < n) ? g_in_deg[i] : 0;
    int ex = block_excl_scan(v, ws) + g_boff[blockIdx.x];
    if (i < n) {
        g_row_start[i] = ex;
        g_cursor[i]    = ex;
        if (i == n - 1) g_row_start[n] = ex + v;
    }
}

__global__ void k_fill(const int4* __restrict__ src4, const int4* __restrict__ dst4,
                       int e) {
    int i = blockIdx.x * blockDim.x + threadIdx.x;
    int base = i * 4;
    if (base + 3 < e) {
        int4 s = src4[i], d = dst4[i];
        g_esrc[atomicAdd(&g_cursor[d.x], 1)] = s.x;
        g_esrc[atomicAdd(&g_cursor[d.y], 1)] = s.y;
        g_esrc[atomicAdd(&g_cursor[d.z], 1)] = s.z;
        g_esrc[atomicAdd(&g_cursor[d.w], 1)] = s.w;
    } else if (base < e) {
        const int* s = (const int*)src4;
        const int* d = (const int*)dst4;
        for (int j = base; j < e; ++j)
            g_esrc[atomicAdd(&g_cursor[d[j]], 1)] = s[j];
    }
}

// ---------------------------------------------------------------------------
// cp.async A-tile issue (fp16 source).
// ---------------------------------------------------------------------------

__device__ __forceinline__ void issue_tileA(const uint4* __restrict__ A,
                                            uint32_t sbase, int row0, int n) {
    int tid = threadIdx.x;
#pragma unroll
    for (int i = tid; i < 2048; i += 256) {
        int r = i >> 4, g = i & 15;
        int row = row0 + r;
        const uint4* src = A + (size_t)((row < n) ? row : 0) * 16 + g;
        int sz = (row < n) ? 16 : 0;
        cp16(sbase + (r * ASTRIDE + g * 8) * 2, src, sz);
    }
}

// ---------------------------------------------------------------------------
// GEMM core: warp grid 4m x 2n, warp tile 32x64, mma.sync.m16n8k16.
// ---------------------------------------------------------------------------

__device__ __forceinline__ void gemm_block(uint32_t sAb, uint32_t sBb,
                                           int wm, int wn, int lane,
                                           float acc[2][8][4]) {
#pragma unroll
    for (int k0 = 0; k0 < 128; k0 += 16) {
        uint32_t a[2][4];
#pragma unroll
        for (int mt = 0; mt < 2; ++mt) {
            int row = wm + mt * 16 + (lane & 15);
            int col = k0 + (lane >> 4) * 8;
            ldsm_x4(a[mt][0], a[mt][1], a[mt][2], a[mt][3],
                    sAb + (row * ASTRIDE + col) * 2);
        }
#pragma unroll
        for (int np = 0; np < 4; ++np) {
            int nb = wn + np * 16;
            int q  = lane >> 3;
            int nrow = nb + ((q >> 1) << 3) + (lane & 7);
            int ncol = k0 + ((q & 1) << 3);
            uint32_t b[4];
            ldsm_x4(b[0], b[1], b[2], b[3], sBb + (nrow * ASTRIDE + ncol) * 2);
            mma16816(acc[0][2 * np],     a[0], b);
            mma16816(acc[1][2 * np],     a[1], b);
            mma16816(acc[0][2 * np + 1], a[0], b + 2);
            mma16816(acc[1][2 * np + 1], a[1], b + 2);
        }
    }
}

__device__ __forceinline__ void gemm_epilogue(float acc[2][8][4], int row0,
                                              int wm, int wn, int g, int t,
                                              unsigned* __restrict__ yh, int n) {
#pragma unroll
    for (int mt = 0; mt < 2; ++mt) {
        int rl = row0 + wm + mt * 16 + g;
        int rh = rl + 8;
        float sl = (rl < n) ? g_out_norm[rl] : 0.f;
        float sh = (rh < n) ? g_out_norm[rh] : 0.f;
#pragma unroll
        for (int nt = 0; nt < 8; ++nt) {
            int c = wn + nt * 8 + t * 2;
            if (rl < n) {
                __half2 p = __floats2half2_rn(acc[mt][nt][0] * sl, acc[mt][nt][1] * sl);
                yh[rl * 64 + (c >> 1)] = *(unsigned*)&p;
            }
            if (rh < n) {
                __half2 p = __floats2half2_rn(acc[mt][nt][2] * sh, acc[mt][nt][3] * sh);
                yh[rh * 64 + (c >> 1)] = *(unsigned*)&p;
            }
        }
    }
}

// ---------------------------------------------------------------------------
// tc_gemm_f32 (R12 config): single A buffer, in-flight fp32->fp16 convert.
// smem = 2 tiles = 69632.
// ---------------------------------------------------------------------------

#define SMEM_GEMM_F32 (2 * ABYTES)
#define SMEM_GEMM_H16 (3 * ABYTES)
#define SMEM_GEMMZ    (2 * ABYTES + 192 * ASTRIDE * 2)

__global__ void __launch_bounds__(256, 2)
tc_gemm_f32(const float* __restrict__ A, const uint4* __restrict__ Bt,
            unsigned* __restrict__ yh, int n) {
    extern __shared__ char ds[];
    __half* sA = (__half*)ds;
    __half* sB = (__half*)(ds + ABYTES);

    int tid = threadIdx.x, lane = tid & 31, wid = tid >> 5;

#pragma unroll
    for (int i = tid; i < 2048; i += 256) {
        int r = i >> 4, g = i & 15;
        *(uint4*)(sB + r * ASTRIDE + g * 8) = Bt[i];
    }

    uint32_t sAb = (uint32_t)__cvta_generic_to_shared(sA);
    uint32_t sBb = (uint32_t)__cvta_generic_to_shared(sB);
    int wm = (wid & 3) * 32;
    int wn = (wid >> 2) * 64;
    int g = lane >> 2, t = lane & 3;

    int nblk = (n + 127) >> 7;
    for (int rb = blockIdx.x; rb < nblk; rb += gridDim.x) {
        int row0 = rb * 128;

        __syncthreads();   // prev iter's A consumed (and B stores on iter 0)
#pragma unroll
        for (int i = tid; i < 2048; i += 256) {
            int r = i >> 4, gg = i & 15;
            uint4 av = make_uint4(0, 0, 0, 0);
            if (row0 + r < n) {
                const float4* f4 = (const float4*)A + (size_t)(row0 + r) * 32 + gg * 2;
                float4 x0 = f4[0], x1 = f4[1];
                __half2 h0 = __floats2half2_rn(x0.x, x0.y);
                __half2 h1 = __floats2half2_rn(x0.z, x0.w);
                __half2 h2 = __floats2half2_rn(x1.x, x1.y);
                __half2 h3 = __floats2half2_rn(x1.z, x1.w);
                av = make_uint4(*(unsigned*)&h0, *(unsigned*)&h1,
                                *(unsigned*)&h2, *(unsigned*)&h3);
            }
            *(uint4*)(sA + r * ASTRIDE + gg * 8) = av;
        }
        __syncthreads();

        float acc[2][8][4];
#pragma unroll
        for (int mt = 0; mt < 2; ++mt)
#pragma unroll
            for (int nt = 0; nt < 8; ++nt)
#pragma unroll
                for (int q = 0; q < 4; ++q) acc[mt][nt][q] = 0.f;

        gemm_block(sAb, sBb, wm, wn, lane, acc);
        gemm_epilogue(acc, row0, wm, wn, g, t, yh, n);
    }
}

// ---------------------------------------------------------------------------
// tc_gemm_h16 (R13 config): cp.async double-buffered fp16 A.
// smem = 3 tiles = 104448.
// ---------------------------------------------------------------------------

__global__ void __launch_bounds__(256, 2)
tc_gemm_h16(const uint4* __restrict__ A, const uint4* __restrict__ Bt,
            unsigned* __restrict__ yh, int n) {
    extern __shared__ char ds[];
    __half* sB = (__half*)(ds + 2 * ABYTES);

    int tid = threadIdx.x, lane = tid & 31, wid = tid >> 5;

#pragma unroll
    for (int i = tid; i < 2048; i += 256) {
        int r = i >> 4, g = i & 15;
        *(uint4*)(sB + r * ASTRIDE + g * 8) = Bt[i];
    }

    uint32_t sA0 = (uint32_t)__cvta_generic_to_shared(ds);
    uint32_t sBb = (uint32_t)__cvta_generic_to_shared(sB);
    int wm = (wid & 3) * 32;
    int wn = (wid >> 2) * 64;
    int g = lane >> 2, t = lane & 3;

    int nblk = (n + 127) >> 7;
    int rb0 = blockIdx.x;
    if (rb0 < nblk) issue_tileA(A, sA0, rb0 * 128, n);
    CP_COMMIT();

    int cur = 0;
    for (int rb = rb0; rb < nblk; rb += gridDim.x) {
        int row0 = rb * 128;
        int nxt = rb + gridDim.x;
        if (nxt < nblk) {
            issue_tileA(A, sA0 + (cur ^ 1) * ABYTES, nxt * 128, n);
            CP_COMMIT();
            CP_WAIT1();
        } else {
            CP_WAIT0();
        }
        __syncthreads();
        uint32_t sAb = sA0 + cur * ABYTES;

        float acc[2][8][4];
#pragma unroll
        for (int mt = 0; mt < 2; ++mt)
#pragma unroll
            for (int nt = 0; nt < 8; ++nt)
#pragma unroll
                for (int q = 0; q < 4; ++q) acc[mt][nt][q] = 0.f;

        gemm_block(sAb, sBb, wm, wn, lane, acc);
        gemm_epilogue(acc, row0, wm, wn, g, t, yh, n);

        __syncthreads();   // all reads of buf[cur] done before refill
        cur ^= 1;
    }
}

// ---------------------------------------------------------------------------
// tc_gemm_z (persistent, cp.async double-buffered over (rb,p)).
// ---------------------------------------------------------------------------

__global__ void __launch_bounds__(256)
tc_gemm_z(const uint4* __restrict__ H1, const uint4* __restrict__ H2,
          const uint4* __restrict__ H3, unsigned* __restrict__ zh, int n) {
    extern __shared__ char ds[];
    __half* sB = (__half*)(ds + 2 * ABYTES);

    int tid = threadIdx.x, lane = tid & 31, wid = tid >> 5;

#pragma unroll
    for (int i = tid; i < 3072; i += 256) {
        int p = i >> 10, rem = i & 1023;
        int r = rem >> 4, g = rem & 15;
        *(uint4*)(sB + (p * 64 + r) * ASTRIDE + g * 8) = g_wot[r * 48 + p * 16 + g];
    }

    uint32_t sA0 = (uint32_t)__cvta_generic_to_shared(ds);
    uint32_t sBb = (uint32_t)__cvta_generic_to_shared(sB);
    int wm = (wid & 3) * 32;
    int wn = (wid >> 2) * 32;
    int g = lane >> 2, t = lane & 3;

    const uint4* parts[3] = { H1, H2, H3 };
    int nblk = (n + 127) >> 7;
    int rb0 = blockIdx.x;

    if (rb0 < nblk) issue_tileA(parts[0], sA0, rb0 * 128, n);
    CP_COMMIT();

    int cur = 0;
    float acc[2][4][4];

    for (int rb = rb0; rb < nblk; rb += gridDim.x) {
        int row0 = rb * 128;
        for (int p = 0; p < 3; ++p) {
            int np_ = p + 1, nrb = rb;
            if (np_ == 3) { np_ = 0; nrb = rb + gridDim.x; }
            if (nrb < nblk) {
                issue_tileA(parts[np_], sA0 + (cur ^ 1) * ABYTES, nrb * 128, n);
                CP_COMMIT();
                CP_WAIT1();
            } else {
                CP_WAIT0();
            }
            __syncthreads();
            uint32_t sAb = sA0 + cur * ABYTES;

            if (p == 0) {
#pragma unroll
                for (int mt = 0; mt < 2; ++mt)
#pragma unroll
                    for (int nt = 0; nt < 4; ++nt)
#pragma unroll
                        for (int q = 0; q < 4; ++q) acc[mt][nt][q] = 0.f;
            }

#pragma unroll
            for (int k0 = 0; k0 < 128; k0 += 16) {
                uint32_t a[2][4];
#pragma unroll
                for (int mt = 0; mt < 2; ++mt) {
                    int row = wm + mt * 16 + (lane & 15);
                    int col = k0 + (lane >> 4) * 8;
                    ldsm_x4(a[mt][0], a[mt][1], a[mt][2], a[mt][3],
                            sAb + (row * ASTRIDE + col) * 2);
                }
#pragma unroll
                for (int np2 = 0; np2 < 2; ++np2) {
                    int nb = p * 64 + wn + np2 * 16;
                    int q  = lane >> 3;
                    int nrow = nb + ((q >> 1) << 3) + (lane & 7);
                    int ncol = k0 + ((q & 1) << 3);
                    uint32_t b[4];
                    ldsm_x4(b[0], b[1], b[2], b[3], sBb + (nrow * ASTRIDE + ncol) * 2);
                    mma16816(acc[0][2 * np2],     a[0], b);
                    mma16816(acc[1][2 * np2],     a[1], b);
                    mma16816(acc[0][2 * np2 + 1], a[0], b + 2);
                    mma16816(acc[1][2 * np2 + 1], a[1], b + 2);
                }
            }

            if (p == 2) {
#pragma unroll
                for (int mt = 0; mt < 2; ++mt) {
                    int rl = row0 + wm + mt * 16 + g;
                    int rh = rl + 8;
#pragma unroll
                    for (int nt = 0; nt < 4; ++nt) {
                        int c = wn + nt * 8 + t * 2;
                        if (rl < n) {
                            __half2 pp = __floats2half2_rn(acc[mt][nt][0], acc[mt][nt][1]);
                            zh[rl * 32 + (c >> 1)] = *(unsigned*)&pp;
                        }
                        if (rh < n) {
                            __half2 pp = __floats2half2_rn(acc[mt][nt][2], acc[mt][nt][3]);
                            zh[rh * 32 + (c >> 1)] = *(unsigned*)&pp;
                        }
                    }
                }
            }
            __syncthreads();
            cur ^= 1;
        }
    }
}

// ---------------------------------------------------------------------------
// Aggregation (128-wide): half-warp per node, x4 unroll (R12 config).
// ---------------------------------------------------------------------------

__device__ __forceinline__ void add_h8(float* acc, uint4 u) {
    float2 f0 = __half22float2(*(__half2*)&u.x);
    float2 f1 = __half22float2(*(__half2*)&u.y);
    float2 f2 = __half22float2(*(__half2*)&u.z);
    float2 f3 = __half22float2(*(__half2*)&u.w);
    acc[0] += f0.x; acc[1] += f0.y; acc[2] += f1.x; acc[3] += f1.y;
    acc[4] += f2.x; acc[5] += f2.y; acc[6] += f3.x; acc[7] += f3.y;
}

__global__ void __launch_bounds__(256) agg128(const uint4* __restrict__ yh4,
                                              const float* __restrict__ bias,
                                              uint4* __restrict__ h, int n) {
    int node = (blockIdx.x * blockDim.x + threadIdx.x) >> 4;
    int l    = threadIdx.x & 15;
    if (node >= n) return;

    int s0 = g_row_start[node];
    int s1 = g_row_start[node + 1];

    float acc[8] = {0.f, 0.f, 0.f, 0.f, 0.f, 0.f, 0.f, 0.f};
    int e = s0;
    for (; e + 4 <= s1; e += 4) {
        int i0 = __ldg(&g_esrc[e]);
        int i1 = __ldg(&g_esrc[e + 1]);
        int i2 = __ldg(&g_esrc[e + 2]);
        int i3 = __ldg(&g_esrc[e + 3]);
        uint4 a = yh4[i0 * 16 + l];
        uint4 b = yh4[i1 * 16 + l];
        uint4 c = yh4[i2 * 16 + l];
        uint4 d = yh4[i3 * 16 + l];
        add_h8(acc, a); add_h8(acc, b); add_h8(acc, c); add_h8(acc, d);
    }
    for (; e < s1; ++e) add_h8(acc, yh4[__ldg(&g_esrc[e]) * 16 + l]);

    float nv = g_in_norm[node];
    float4 b0 = ((const float4*)bias)[2 * l];
    float4 b1 = ((const float4*)bias)[2 * l + 1];
    float o0 = fmaxf(acc[0] * nv + b0.x, 0.f);
    float o1 = fmaxf(acc[1] * nv + b0.y, 0.f);
    float o2 = fmaxf(acc[2] * nv + b0.z, 0.f);
    float o3 = fmaxf(acc[3] * nv + b0.w, 0.f);
    float o4 = fmaxf(acc[4] * nv + b1.x, 0.f);
    float o5 = fmaxf(acc[5] * nv + b1.y, 0.f);
    float o6 = fmaxf(acc[6] * nv + b1.z, 0.f);
    float o7 = fmaxf(acc[7] * nv + b1.w, 0.f);
    __half2 p0 = __floats2half2_rn(o0, o1);
    __half2 p1 = __floats2half2_rn(o2, o3);
    __half2 p2 = __floats2half2_rn(o4, o5);
    __half2 p3 = __floats2half2_rn(o6, o7);
    h[node * 16 + l] = make_uint4(*(unsigned*)&p0, *(unsigned*)&p1,
                                  *(unsigned*)&p2, *(unsigned*)&p3);
}

// ---------------------------------------------------------------------------
// Final pooling (64-wide): half-warp per node, x4 unroll, fp32 out.
// ---------------------------------------------------------------------------

__global__ void __launch_bounds__(256) agg64(const uint2* __restrict__ zh2,
                                             const float* __restrict__ bo,
                                             float* __restrict__ out, int n) {
    int node = (blockIdx.x * blockDim.x + threadIdx.x) >> 4;
    int l    = threadIdx.x & 15;
    if (node >= n) return;

    int s0 = g_row_start[node];
    int s1 = g_row_start[node + 1];

    float4 acc = make_float4(0.f, 0.f, 0.f, 0.f);
    int e = s0;
    for (; e + 4 <= s1; e += 4) {
        int i0 = __ldg(&g_esrc[e]);
        int i1 = __ldg(&g_esrc[e + 1]);
        int i2 = __ldg(&g_esrc[e + 2]);
        int i3 = __ldg(&g_esrc[e + 3]);
        uint2 a = zh2[i0 * 16 + l];
        uint2 b = zh2[i1 * 16 + l];
        uint2 c = zh2[i2 * 16 + l];
        uint2 d = zh2[i3 * 16 + l];
        float2 fa0 = __half22float2(*(__half2*)&a.x);
        float2 fa1 = __half22float2(*(__half2*)&a.y);
        float2 fb0 = __half22float2(*(__half2*)&b.x);
        float2 fb1 = __half22float2(*(__half2*)&b.y);
        float2 fc0 = __half22float2(*(__half2*)&c.x);
        float2 fc1 = __half22float2(*(__half2*)&c.y);
        float2 fd0 = __half22float2(*(__half2*)&d.x);
        float2 fd1 = __half22float2(*(__half2*)&d.y);
        acc.x += (fa0.x + fb0.x) + (fc0.x + fd0.x);
        acc.y += (fa0.y + fb0.y) + (fc0.y + fd0.y);
        acc.z += (fa1.x + fb1.x) + (fc1.x + fd1.x);
        acc.w += (fa1.y + fb1.y) + (fc1.y + fd1.y);
    }
    for (; e < s1; ++e) {
        uint2 a = zh2[__ldg(&g_esrc[e]) * 16 + l];
        float2 fa0 = __half22float2(*(__half2*)&a.x);
        float2 fa1 = __half22float2(*(__half2*)&a.y);
        acc.x += fa0.x; acc.y += fa0.y; acc.z += fa1.x; acc.w += fa1.y;
    }

    float4 bb = ((const float4*)bo)[l];
    ((float4*)out)[node * 16 + l] =
        make_float4(acc.x + bb.x, acc.y + bb.y, acc.z + bb.z, acc.w + bb.w);
}

// ---------------------------------------------------------------------------
// Launcher
// ---------------------------------------------------------------------------

extern "C" void kernel_launch(void* const* d_in, const int* in_sizes, int n_in,
                              void* d_out, int out_size) {
    const float* feats = (const float*)d_in[0];
    const int*   src   = (const int*)  d_in[1];
    const int*   dst   = (const int*)  d_in[2];
    const float* W0    = (const float*)d_in[3];
    const float* b0    = (const float*)d_in[4];
    const float* W1    = (const float*)d_in[5];
    const float* b1    = (const float*)d_in[6];
    const float* W2    = (const float*)d_in[7];
    const float* b2    = (const float*)d_in[8];
    const float* Wo    = (const float*)d_in[9];
    const float* bo    = (const float*)d_in[10];
    float* out = (float*)d_out;

    int n = in_sizes[0] / 128;
    int e = in_sizes[1];

    cudaFuncSetAttribute(tc_gemm_f32, cudaFuncAttributeMaxDynamicSharedMemorySize, SMEM_GEMM_F32);
    cudaFuncSetAttribute(tc_gemm_h16, cudaFuncAttributeMaxDynamicSharedMemorySize, SMEM_GEMM_H16);
    cudaFuncSetAttribute(tc_gemm_z,   cudaFuncAttributeMaxDynamicSharedMemorySize, SMEM_GEMMZ);

    uint4 *h1, *h2, *h3, *yh4, *w0t, *w1t, *w2t;
    uint2 *zh2;
    cudaGetSymbolAddress((void**)&h1,  g_h1);
    cudaGetSymbolAddress((void**)&h2,  g_h2);
    cudaGetSymbolAddress((void**)&h3,  g_h3);
    cudaGetSymbolAddress((void**)&yh4, g_yh);
    cudaGetSymbolAddress((void**)&zh2, g_zh);
    cudaGetSymbolAddress((void**)&w0t, g_w0t);
    cudaGetSymbolAddress((void**)&w1t, g_w1t);
    cudaGetSymbolAddress((void**)&w2t, g_w2t);

    int nb  = (n + 255) / 256;
    int eb4 = (e / 4 + 255) / 256;
    int sb  = (n + SCAN_B - 1) / SCAN_B;
    int cb  = (n + 73728 + 255) / 256;    // norms + weight conversion
    int ab  = (n + 15) / 16;

    // Degrees -> norms+weights -> gemm1 (4th launch, profiled) -> CSR.
    k_zero_deg<<<nb, 256>>>(n);
    k_count<<<eb4, 256>>>((const int4*)src, (const int4*)dst, e);
    k_norm_cvt<<<cb, 256>>>(W0, W1, W2, Wo, n);
    tc_gemm_f32<<<GEMM_GRID, 256, SMEM_GEMM_F32>>>(feats, w0t, (unsigned*)yh4, n);
    k_bsums<<<sb, 1024>>>(n);
    k_scan_bsums<<<1, 1024>>>(sb);
    k_write_csr<<<sb, 1024>>>(n);
    k_fill<<<eb4, 256>>>((const int4*)src, (const int4*)dst, e);

    // Layer 1 aggregation -> h1 (fp16)
    agg128<<<ab, 256>>>(yh4, b0, h1, n);
    // Layer 2
    tc_gemm_h16<<<GEMM_GRID, 256, SMEM_GEMM_H16>>>(h1, w1t, (unsigned*)yh4, n);
    agg128<<<ab, 256>>>(yh4, b1, h2, n);
    // Layer 3
    tc_gemm_h16<<<GEMM_GRID, 256, SMEM_GEMM_H16>>>(h2, w2t, (unsigned*)yh4, n);
    agg128<<<ab, 256>>>(yh4, b2, h3, n);

    // Output projection (JK-cat folded) + final pooling
    tc_gemm_z<<<148, 256, SMEM_GEMMZ>>>(h1, h2, h3, (unsigned*)zh2, n);
    agg64<<<ab, 256>>>(zh2, bo, out, n);
}